// round 15
// baseline (speedup 1.0000x reference)
#include <cuda_runtime.h>
#include <math.h>
#include <stdint.h>
#include <stddef.h>

// ---------------- problem constants ----------------
#define Bn   32
#define Tn   1024
#define Dn   1024
#define Sn   256
#define KF   3
#define Mrows (Bn*Tn)                 // 32768
#define IOFF  ((size_t)Bn*Tn*Dn)      // indices start in d_out
#define LOFF  (IOFF + (size_t)Bn*Tn)  // total scalar slot

// ---------------- GRU config: W-in-registers --------------------------------
#define GCTAS    147                  // CTA owns 7 d-columns
#define DPC3     7
#define GTHREADS 448                  // 14 warps = 7 d x 2 k-halves
#define MG_OFF3  (Dn*Bn)              // after 128KB h tile
#define GRU_SMEM3 ((MG_OFF3 + 42*32) * 4)   // 136448 B

// ---------------- device scratch (no allocations) ----------------
__device__ float g_dots[(size_t)Mrows * Sn];     // 2*F.C^T
__device__ float g_Hbuf[(size_t)(Tn+1)*Bn*Dn];   // h history, slot 0 = zeros
__device__ float g_Hp  [(size_t)Mrows * Dn];
__device__ float g_GI  [(size_t)Sn * 3*Dn];      // codebook @ W_ih^T + b_ih
__device__ float g_hkb [2][Dn*Bn];               // double-buffered h, [k][b]
__device__ float g_rnorm[Mrows];
__device__ float g_cnorm[Sn];
__device__ float g_zbias[Sn];
__device__ int   g_idx[Mrows];                   // row = b*Tn + t
__device__ float g_mse_arr[Mrows/8];
__device__ float g_cp_arr[KF*(Tn-1)];
__device__ unsigned g_ctr[16*64];                // distributed barrier counters

// ---------------- launch #1: rownorms + h/ctr init -----------------------------
__global__ void prep_kernel(const float* __restrict__ features,
                            const float* __restrict__ codebook) {
    int bx = blockIdx.x;
    if (bx < 4096 + 32) {
        const float* X = (bx < 4096) ? features : codebook;
        float* out     = (bx < 4096) ? g_rnorm : g_cnorm;
        int base       = (bx < 4096) ? bx * 8 : (bx - 4096) * 8;
        int wid = threadIdx.x >> 5, lane = threadIdx.x & 31;
        int row = base + wid;
        const float4* x = (const float4*)(X + (size_t)row * Dn);
        float s = 0.f;
#pragma unroll
        for (int j = 0; j < 8; j++) {
            float4 v = x[j*32 + lane];
            s += v.x*v.x + v.y*v.y + v.z*v.z + v.w*v.w;
        }
#pragma unroll
        for (int off = 16; off; off >>= 1) s += __shfl_xor_sync(0xffffffffu, s, off);
        if (lane == 0) out[row] = s;
    } else {
        int i = (bx - 4128) * 256 + threadIdx.x;
        if (i < Bn*Dn)        g_Hbuf[i] = 0.f;        // slot 0 = h(0) = 0
        else if (i < 2*Bn*Dn) g_hkb[0][i - Bn*Dn] = 0.f;
        if (i < 16*64)        g_ctr[i] = 0u;
    }
}

// ---------------- launch #2: fused SGEMM (dots + GI) ---------------------------
// C = alpha*A*B^T + bias[col]; FFMA chain identical to the proven kernel ->
// dots (hence argmin/indices) bit-identical.
#define DOTS_BLKS 512
__global__ __launch_bounds__(256, 2)
void sgemm_fused(const float* __restrict__ A1, const float* __restrict__ B1,
                 float* __restrict__ C1, const float* __restrict__ bias1,
                 int K1, float alpha1, int N1,
                 const float* __restrict__ A2, const float* __restrict__ B2,
                 float* __restrict__ C2, const float* __restrict__ bias2,
                 int K2, float alpha2, int N2)
{
    __shared__ float As[16][128];
    __shared__ float Bs[16][128];
    const int tid = threadIdx.x;
    const int tx = tid & 15, ty = tid >> 4;

    const float *A, *Bm, *bias; float *C;
    int K, N, bxn, byn; float alpha;
    if (blockIdx.x < DOTS_BLKS) {
        A = A1; Bm = B1; C = C1; bias = bias1; K = K1; N = N1; alpha = alpha1;
        bxn = blockIdx.x & 1;  byn = blockIdx.x >> 1;
    } else {
        int i = blockIdx.x - DOTS_BLKS;
        A = A2; Bm = B2; C = C2; bias = bias2; K = K2; N = N2; alpha = alpha2;
        bxn = i % 24;          byn = i / 24;
    }
    const float* Ab = A  + (size_t)byn * 128 * K;
    const float* Bb = Bm + (size_t)bxn * 128 * K;

    float acc[8][8];
#pragma unroll
    for (int i = 0; i < 8; i++)
#pragma unroll
        for (int j = 0; j < 8; j++) acc[i][j] = 0.f;

    for (int kt = 0; kt < K; kt += 16) {
#pragma unroll
        for (int r = 0; r < 2; r++) {
            int f   = tid + r * 256;
            int row = f >> 2;
            int c4  = (f & 3) << 2;
            float4 va = *(const float4*)(Ab + (size_t)row * K + kt + c4);
            As[c4+0][row] = va.x; As[c4+1][row] = va.y;
            As[c4+2][row] = va.z; As[c4+3][row] = va.w;
            float4 vb = *(const float4*)(Bb + (size_t)row * K + kt + c4);
            Bs[c4+0][row] = vb.x; Bs[c4+1][row] = vb.y;
            Bs[c4+2][row] = vb.z; Bs[c4+3][row] = vb.w;
        }
        __syncthreads();
#pragma unroll
        for (int kk = 0; kk < 16; kk++) {
            float a[8], b[8];
            *(float4*)&a[0] = *(const float4*)&As[kk][ty*8];
            *(float4*)&a[4] = *(const float4*)&As[kk][ty*8+4];
            *(float4*)&b[0] = *(const float4*)&Bs[kk][tx*8];
            *(float4*)&b[4] = *(const float4*)&Bs[kk][tx*8+4];
#pragma unroll
            for (int i = 0; i < 8; i++)
#pragma unroll
                for (int j = 0; j < 8; j++) acc[i][j] += a[i] * b[j];
        }
        __syncthreads();
    }
#pragma unroll
    for (int i = 0; i < 8; i++) {
        size_t row = (size_t)byn * 128 + ty*8 + i;
#pragma unroll
        for (int j = 0; j < 8; j += 4) {
            int col = bxn * 128 + tx*8 + j;
            float4 o;
            o.x = alpha * acc[i][j+0] + bias[col+0];
            o.y = alpha * acc[i][j+1] + bias[col+1];
            o.z = alpha * acc[i][j+2] + bias[col+2];
            o.w = alpha * acc[i][j+3] + bias[col+3];
            *(float4*)(C + row * (size_t)N + col) = o;
        }
    }
}

// ---------------- plain SGEMM (Hp) — proven fp32-roofline version ---------------
__global__ __launch_bounds__(256, 2)
void sgemm_nt(const float* __restrict__ A, const float* __restrict__ Bm,
              float* __restrict__ C, const float* __restrict__ bias,
              int M, int N, int K, float alpha)
{
    __shared__ float As[16][128];
    __shared__ float Bs[16][128];
    const int tid = threadIdx.x;
    const int tx = tid & 15, ty = tid >> 4;
    const float* Ab = A + (size_t)blockIdx.y * 128 * K;
    const float* Bb = Bm + (size_t)blockIdx.x * 128 * K;

    float acc[8][8];
#pragma unroll
    for (int i = 0; i < 8; i++)
#pragma unroll
        for (int j = 0; j < 8; j++) acc[i][j] = 0.f;

    for (int kt = 0; kt < K; kt += 16) {
#pragma unroll
        for (int r = 0; r < 2; r++) {
            int f   = tid + r * 256;
            int row = f >> 2;
            int c4  = (f & 3) << 2;
            float4 va = *(const float4*)(Ab + (size_t)row * K + kt + c4);
            As[c4+0][row] = va.x; As[c4+1][row] = va.y;
            As[c4+2][row] = va.z; As[c4+3][row] = va.w;
            float4 vb = *(const float4*)(Bb + (size_t)row * K + kt + c4);
            Bs[c4+0][row] = vb.x; Bs[c4+1][row] = vb.y;
            Bs[c4+2][row] = vb.z; Bs[c4+3][row] = vb.w;
        }
        __syncthreads();
#pragma unroll
        for (int kk = 0; kk < 16; kk++) {
            float a[8], b[8];
            *(float4*)&a[0] = *(const float4*)&As[kk][ty*8];
            *(float4*)&a[4] = *(const float4*)&As[kk][ty*8+4];
            *(float4*)&b[0] = *(const float4*)&Bs[kk][tx*8];
            *(float4*)&b[4] = *(const float4*)&Bs[kk][tx*8+4];
#pragma unroll
            for (int i = 0; i < 8; i++)
#pragma unroll
                for (int j = 0; j < 8; j++) acc[i][j] += a[i] * b[j];
        }
        __syncthreads();
    }
#pragma unroll
    for (int i = 0; i < 8; i++) {
        size_t row = (size_t)blockIdx.y * 128 + ty*8 + i;
#pragma unroll
        for (int j = 0; j < 8; j += 4) {
            int col = blockIdx.x * 128 + tx*8 + j;
            float4 o;
            o.x = alpha * acc[i][j+0] + bias[col+0];
            o.y = alpha * acc[i][j+1] + bias[col+1];
            o.z = alpha * acc[i][j+2] + bias[col+2];
            o.w = alpha * acc[i][j+3] + bias[col+3];
            *(float4*)(C + row * (size_t)N + col) = o;
        }
    }
}

// ---------------- launch #3: argmin (reference-exact) + gather + mse -----------
__global__ void argmin_kernel(const float* __restrict__ codebook,
                              float* __restrict__ dout) {
    int wid = threadIdx.x >> 5, lane = threadIdx.x & 31;
    int row = blockIdx.x * 8 + wid;
    __shared__ float part[8];
    __shared__ float cn_s[Sn];
    if (threadIdx.x < Sn) cn_s[threadIdx.x] = g_cnorm[threadIdx.x];
    __syncthreads();

    const float rn = g_rnorm[row];
    float bv = 3.4e38f; int bi = 0;
#pragma unroll
    for (int j = 0; j < 8; j++) {
        int i = j * 32 + lane;
        float dot2 = g_dots[(size_t)row * Sn + i];
        float v = __fadd_rn(__fsub_rn(rn, dot2), cn_s[i]);
        if (v < bv) { bv = v; bi = i; }
    }
#pragma unroll
    for (int off = 16; off; off >>= 1) {
        float ov = __shfl_xor_sync(0xffffffffu, bv, off);
        int   oi = __shfl_xor_sync(0xffffffffu, bi, off);
        if (ov < bv || (ov == bv && oi < bi)) { bv = ov; bi = oi; }
    }
    if (lane == 0) {
        g_idx[row] = bi;
        dout[IOFF + row] = (float)bi;
        part[wid] = bv;
    }
    const float4* c4 = (const float4*)(codebook + (size_t)bi * Dn);
    float4* o4 = (float4*)(dout + (size_t)row * Dn);
#pragma unroll
    for (int j = 0; j < 8; j++) o4[j*32 + lane] = __ldg(c4 + j*32 + lane);

    __syncthreads();
    if (threadIdx.x == 0) {
        float s = 0.f;
#pragma unroll
        for (int w = 0; w < 8; w++) s += part[w];
        g_mse_arr[blockIdx.x] = s;
    }
}

// ---------------- launch #4 (profiled): persistent GRU, W in registers ---------
// 147 CTAs; CTA owns d in [7*bid, 7*bid+7) = 21 gate-rows. Warp = (dl, kh):
// lane l owns k = kh*512 + 32j + l (j<16); W[3 gates][16 j] lives in registers
// for the whole kernel. h staged to smem [k][b] with XOR swizzle (b ^ (k&31))
// -> stride-32-k scalar LDS conflict-free. Per b: 16 LDS + 48 FFMA + butterfly.
// kh halves merged in smem; kh==0 warps run gates. One distributed barrier.
__device__ __forceinline__ unsigned ld_relaxed_u32(const unsigned* p) {
    unsigned v;
    asm volatile("ld.relaxed.gpu.u32 %0, [%1];" : "=r"(v) : "l"(p) : "memory");
    return v;
}

__global__ __launch_bounds__(GTHREADS, 1)
void gru_step(const float* __restrict__ Wf, const float* __restrict__ bhh)
{
    extern __shared__ float sm[];
    float* hs = sm;                          // [1024][32] swizzled h (128 KB)
    float* mg = sm + MG_OFF3;                // [2*21][32] kh partials

    const int tid  = threadIdx.x;
    const int w    = tid >> 5, lane = tid & 31;
    const int dl   = w >> 1;                 // 0..6
    const int kh   = w & 1;                  // k-half
    const int d0   = blockIdx.x * DPC3;
    const int d    = d0 + dl;
    const bool act = (d < Dn);

    // ---- W slice into registers (once) ----
    float wr[3][16];
    {
        int dc = act ? d : (Dn - 1);
#pragma unroll
        for (int g = 0; g < 3; g++) {
            const float* Wp = Wf + ((size_t)(g * Dn + dc)) * Dn + kh * 512 + lane;
#pragma unroll
            for (int j = 0; j < 16; j++) wr[g][j] = __ldg(Wp + j * 32);
        }
    }
    // gate-role biases (kh==0 warps; lane = b does all 32 b, needs per-d bias)
    float bh0 = 0.f, bh1 = 0.f, bh2 = 0.f;
    if (act && kh == 0) {
        bh0 = __ldg(bhh + d);
        bh1 = __ldg(bhh + Dn + d);
        bh2 = __ldg(bhh + 2 * Dn + d);
    }

    for (int t = 0; t < Tn; t++) {
        const float* hk  = g_hkb[t & 1];
        float*       hnx = g_hkb[(t + 1) & 1];

        // gate prefetch (kh==0 warps): code, GI, hprev — hidden under GEMM
        float gi0 = 0.f, gi1 = 0.f, gi2 = 0.f, hprev = 0.f;
        if (act && kh == 0) {
            int code = __ldg(g_idx + lane * Tn + t);
            const float* gi = g_GI + (size_t)code * (3 * Dn);
            gi0   = __ldcg(gi + d);
            gi1   = __ldcg(gi + Dn + d);
            gi2   = __ldcg(gi + 2 * Dn + d);
            hprev = __ldcg(hk + d * 32 + lane);
        }

        // ---- stage h (full 128 KB) with XOR swizzle ----
        for (int i = tid; i < Bn * Dn / 4; i += GTHREADS) {
            int k = i >> 3, bq = (i & 7) * 4;
            float4 v = __ldcg((const float4*)(hk + (size_t)i * 4));
            int x = k & 31;
            float* row = hs + k * 32;
            row[(bq + 0) ^ x] = v.x;
            row[(bq + 1) ^ x] = v.y;
            row[(bq + 2) ^ x] = v.z;
            row[(bq + 3) ^ x] = v.w;
        }
        __syncthreads();

        // ---- GEMM: 3 gates x 32 b over this lane's 16 k's ----
        if (act) {
            const float* hb = hs + (kh * 512 + lane) * 32;
#pragma unroll 2
            for (int b = 0; b < Bn; b++) {
                const float* hp2 = hb + (b ^ lane);
                float a0 = 0.f, a1 = 0.f, a2 = 0.f;
#pragma unroll
                for (int j = 0; j < 16; j++) {
                    float hv = hp2[j * 1024];
                    a0 += wr[0][j] * hv;
                    a1 += wr[1][j] * hv;
                    a2 += wr[2][j] * hv;
                }
#pragma unroll
                for (int off = 16; off; off >>= 1) {
                    a0 += __shfl_xor_sync(0xffffffffu, a0, off);
                    a1 += __shfl_xor_sync(0xffffffffu, a1, off);
                    a2 += __shfl_xor_sync(0xffffffffu, a2, off);
                }
                if (lane < 3) {
                    float v = (lane == 0) ? a0 : (lane == 1) ? a1 : a2;
                    mg[(kh * 21 + dl * 3 + lane) * 32 + b] = v;
                }
            }
        }
        __syncthreads();

        // ---- gates (kh==0 warps): d fixed, b = lane ----
        if (act && kh == 0) {
            int r0 = dl * 3;
            float sr = mg[(r0 + 0) * 32 + lane] + mg[(21 + r0 + 0) * 32 + lane];
            float sz = mg[(r0 + 1) * 32 + lane] + mg[(21 + r0 + 1) * 32 + lane];
            float sn = mg[(r0 + 2) * 32 + lane] + mg[(21 + r0 + 2) * 32 + lane];
            float r = 1.f / (1.f + expf(-(sr + bh0 + gi0)));
            float z = 1.f / (1.f + expf(-(sz + bh1 + gi1)));
            float n = tanhf(gi2 + r * (sn + bh2));
            float hn = (1.f - z) * n + z * hprev;
            hnx[d * 32 + lane] = hn;
            g_Hbuf[(size_t)(t + 1) * (Bn * Dn) + lane * Dn + d] = hn;
        }
        __syncthreads();

        // ---- single distributed-counter barrier ----
        if (tid == 0) {
            __threadfence();                         // release CTA's h writes
            atomicAdd(&g_ctr[(blockIdx.x & 15) * 64], 1u);
            unsigned tgt = (unsigned)GCTAS * (unsigned)(t + 1);
            unsigned s;
            do {
                s = 0;
#pragma unroll
                for (int i = 0; i < 16; i++) s += ld_relaxed_u32(&g_ctr[i * 64]);
            } while (s < tgt);
            __threadfence();                         // acquire
        }
        __syncthreads();
    }
}

// ---------------- CP loss per (k,t) ---------------------------------------------
__global__ void cploss_kernel(const float* __restrict__ features,
                              const int* __restrict__ neg_idx)
{
    int t  = blockIdx.x;
    int kf = blockIdx.y;
    int k  = kf + 1;
    int slot = kf * (Tn - 1) + t;
    if (t >= Tn - k) { if (threadIdx.x == 0) g_cp_arr[slot] = 0.f; return; }

    __shared__ float sig_s[Bn];
    int wid = threadIdx.x >> 5, lane = threadIdx.x & 31;
#pragma unroll
    for (int bi = 0; bi < 4; bi++) {
        int b = wid * 4 + bi;
        const float4* hp = (const float4*)(g_Hp + ((size_t)t * Bn + b) * Dn);
        const float4* fp = (const float4*)(features + ((size_t)b * Tn + (t + k)) * Dn);
        int bneg = neg_idx[((size_t)kf * Tn + t) * Bn + b];
        const float4* fn = (const float4*)(features + ((size_t)bneg * Tn + t) * Dn);
        float s = 0.f;
#pragma unroll
        for (int j = 0; j < 8; j++) {
            float4 h4 = hp[j*32 + lane];
            float4 p4 = fp[j*32 + lane];
            float4 n4 = fn[j*32 + lane];
            s += h4.x*(p4.x-n4.x) + h4.y*(p4.y-n4.y)
               + h4.z*(p4.z-n4.z) + h4.w*(p4.w-n4.w);
        }
#pragma unroll
        for (int off = 16; off; off >>= 1) s += __shfl_xor_sync(0xffffffffu, s, off);
        if (lane == 0) sig_s[b] = 1.f / (1.f + expf(-s));
    }
    __syncthreads();
    if (threadIdx.x == 0) {
        float m = 0.f;
#pragma unroll
        for (int b = 0; b < Bn; b++) m += sig_s[b];
        g_cp_arr[slot] = -logf(m * (1.f / (float)Bn));
    }
}

// ---------------- final deterministic reduction ----------------------------------
__global__ void finalize_kernel(float* __restrict__ dout) {
    __shared__ float red[256];
    int tid = threadIdx.x;
    float s = 0.f;
    for (int i = tid; i < KF*(Tn-1); i += 256) s += g_cp_arr[i];
    red[tid] = s; __syncthreads();
    for (int o = 128; o; o >>= 1) { if (tid < o) red[tid] += red[tid+o]; __syncthreads(); }
    float cp = red[0]; __syncthreads();
    float m = 0.f;
    for (int i = tid; i < Mrows/8; i += 256) m += g_mse_arr[i];
    red[tid] = m; __syncthreads();
    for (int o = 128; o; o >>= 1) { if (tid < o) red[tid] += red[tid+o]; __syncthreads(); }
    if (tid == 0) {
        float mse = red[0] / ((float)Mrows * (float)Dn);
        dout[LOFF] = cp / (float)(KF * (Tn - KF)) + 1.25f * mse;
    }
}

// ---------------- launch ----------------------------------------------------------
extern "C" void kernel_launch(void* const* d_in, const int* in_sizes, int n_in,
                              void* d_out, int out_size) {
    (void)in_sizes; (void)n_in; (void)out_size;
    const float* features = (const float*)d_in[0];
    const float* codebook = (const float*)d_in[1];
    const float* W_ih     = (const float*)d_in[2];
    const float* W_hh     = (const float*)d_in[3];
    const float* b_ih     = (const float*)d_in[4];
    const float* b_hh     = (const float*)d_in[5];
    const float* W_p      = (const float*)d_in[6];
    const float* b_p      = (const float*)d_in[7];
    const int*   neg_idx  = (const int*)d_in[8];
    float* dout = (float*)d_out;

    void *p_dots, *p_GI, *p_Hbuf, *p_Hp, *p_zb;
    cudaGetSymbolAddress(&p_dots, g_dots);
    cudaGetSymbolAddress(&p_GI,   g_GI);
    cudaGetSymbolAddress(&p_Hbuf, g_Hbuf);
    cudaGetSymbolAddress(&p_Hp,   g_Hp);
    cudaGetSymbolAddress(&p_zb,   g_zbias);
    const float* p_H = (const float*)p_Hbuf + (size_t)Bn * Dn;  // slots 1..Tn

    cudaFuncSetAttribute(gru_step,
        cudaFuncAttributeMaxDynamicSharedMemorySize, GRU_SMEM3);

    // #1: rownorms + h/ctr init
    prep_kernel<<<4096 + 32 + 256, 256>>>(features, codebook);

    // #2: fused GEMM — dots = 2*F C^T (bit-identical chain) and GI
    sgemm_fused<<<DOTS_BLKS + 48, 256>>>(
        features, codebook, (float*)p_dots, (const float*)p_zb, Dn, 2.0f, Sn,
        codebook, W_ih,     (float*)p_GI,   b_ih,               Dn, 1.0f, 3*Dn);

    // #3: argmin + quantized gather + mse partials
    argmin_kernel<<<Mrows/8, 256>>>(codebook, dout);

    // #4 (profiled): persistent GRU, W in registers
    gru_step<<<GCTAS, GTHREADS, GRU_SMEM3>>>(W_hh, b_hh);

    // #5: Hp = H @ W_p^T + b_p
    sgemm_nt<<<dim3(Dn/128, Mrows/128), 256>>>(
        p_H, W_p, (float*)p_Hp, b_p, Mrows, Dn, Dn, 1.0f);

    // #6: CP loss terms
    cploss_kernel<<<dim3(Tn-1, KF), 256>>>(features, neg_idx);

    // #7: deterministic final reduction
    finalize_kernel<<<1, 256>>>(dout);
}

// round 16
// speedup vs baseline: 1.4607x; 1.4607x over previous
#include <cuda_runtime.h>
#include <math.h>
#include <stdint.h>
#include <stddef.h>

// ---------------- problem constants ----------------
#define Bn   32
#define Tn   1024
#define Dn   1024
#define Sn   256
#define KF   3
#define Mrows (Bn*Tn)                 // 32768
#define IOFF  ((size_t)Bn*Tn*Dn)      // indices start in d_out
#define LOFF  (IOFF + (size_t)Bn*Tn)  // total scalar slot

// ---------------- GRU step-GEMM config (R13 shape) ----------------
#define GCTAS   144                   // 24 m-tiles x 6 k-splits
#define WS_STRIDE 132                 // padded W smem row (floats)
#define HS_STRIDE 36                  // padded h smem row (floats)
#define WS_OFF  0
#define HS_OFF  (176*WS_STRIDE)                  // 23232
#define MG_OFF  (HS_OFF + 176*HS_STRIDE)         // 29568
#define GRU_SMEM ((MG_OFF + 128*36)*4)           // 136704 B

// ---------------- device scratch (no allocations) ----------------
__device__ float g_dots[(size_t)Mrows * Sn];     // 2*F.C^T
__device__ float g_Hbuf[(size_t)(Tn+1)*Bn*Dn];   // h history, slot 0 = zeros
__device__ float g_Hp  [(size_t)Mrows * Dn];
__device__ float g_GI  [(size_t)Sn * 3*Dn];      // codebook @ W_ih^T + b_ih
__device__ float g_hkb [Dn*Bn];                  // current h transposed [d][b]
__device__ float g_part2[6][3*Dn][Bn];           // k-split gh partials [ks][m][b]
__device__ float g_rnorm[Mrows];
__device__ float g_cnorm[Sn];
__device__ float g_zbias[Sn];
__device__ int   g_idx[Mrows];                   // row = b*Tn + t
__device__ float g_mse_arr[Mrows/8];
__device__ float g_cp_arr[KF*(Tn-1)];
__device__ unsigned g_ctr[16*64];                // distributed barrier counters

// ---------------- launch #1: rownorms + h/ctr init -----------------------------
__global__ void prep_kernel(const float* __restrict__ features,
                            const float* __restrict__ codebook) {
    int bx = blockIdx.x;
    if (bx < 4096 + 32) {
        const float* X = (bx < 4096) ? features : codebook;
        float* out     = (bx < 4096) ? g_rnorm : g_cnorm;
        int base       = (bx < 4096) ? bx * 8 : (bx - 4096) * 8;
        int wid = threadIdx.x >> 5, lane = threadIdx.x & 31;
        int row = base + wid;
        const float4* x = (const float4*)(X + (size_t)row * Dn);
        float s = 0.f;
#pragma unroll
        for (int j = 0; j < 8; j++) {
            float4 v = x[j*32 + lane];
            s += v.x*v.x + v.y*v.y + v.z*v.z + v.w*v.w;
        }
#pragma unroll
        for (int off = 16; off; off >>= 1) s += __shfl_xor_sync(0xffffffffu, s, off);
        if (lane == 0) out[row] = s;
    } else {
        int i = (bx - 4128) * 256 + threadIdx.x;
        if (i < Bn*Dn)        g_Hbuf[i] = 0.f;        // slot 0 = h(0) = 0
        else if (i < 2*Bn*Dn) g_hkb[i - Bn*Dn] = 0.f;
        if (i < 16*64)        g_ctr[i] = 0u;
    }
}

// ---------------- launch #2: fused SGEMM (dots + GI) ---------------------------
// C = alpha*A*B^T + bias[col]; FFMA chain identical to the proven kernel ->
// dots (hence argmin/indices) bit-identical.
#define DOTS_BLKS 512
__global__ __launch_bounds__(256, 2)
void sgemm_fused(const float* __restrict__ A1, const float* __restrict__ B1,
                 float* __restrict__ C1, const float* __restrict__ bias1,
                 int K1, float alpha1, int N1,
                 const float* __restrict__ A2, const float* __restrict__ B2,
                 float* __restrict__ C2, const float* __restrict__ bias2,
                 int K2, float alpha2, int N2)
{
    __shared__ float As[16][128];
    __shared__ float Bs[16][128];
    const int tid = threadIdx.x;
    const int tx = tid & 15, ty = tid >> 4;

    const float *A, *Bm, *bias; float *C;
    int K, N, bxn, byn; float alpha;
    if (blockIdx.x < DOTS_BLKS) {
        A = A1; Bm = B1; C = C1; bias = bias1; K = K1; N = N1; alpha = alpha1;
        bxn = blockIdx.x & 1;  byn = blockIdx.x >> 1;
    } else {
        int i = blockIdx.x - DOTS_BLKS;
        A = A2; Bm = B2; C = C2; bias = bias2; K = K2; N = N2; alpha = alpha2;
        bxn = i % 24;          byn = i / 24;
    }
    const float* Ab = A  + (size_t)byn * 128 * K;
    const float* Bb = Bm + (size_t)bxn * 128 * K;

    float acc[8][8];
#pragma unroll
    for (int i = 0; i < 8; i++)
#pragma unroll
        for (int j = 0; j < 8; j++) acc[i][j] = 0.f;

    for (int kt = 0; kt < K; kt += 16) {
#pragma unroll
        for (int r = 0; r < 2; r++) {
            int f   = tid + r * 256;
            int row = f >> 2;
            int c4  = (f & 3) << 2;
            float4 va = *(const float4*)(Ab + (size_t)row * K + kt + c4);
            As[c4+0][row] = va.x; As[c4+1][row] = va.y;
            As[c4+2][row] = va.z; As[c4+3][row] = va.w;
            float4 vb = *(const float4*)(Bb + (size_t)row * K + kt + c4);
            Bs[c4+0][row] = vb.x; Bs[c4+1][row] = vb.y;
            Bs[c4+2][row] = vb.z; Bs[c4+3][row] = vb.w;
        }
        __syncthreads();
#pragma unroll
        for (int kk = 0; kk < 16; kk++) {
            float a[8], b[8];
            *(float4*)&a[0] = *(const float4*)&As[kk][ty*8];
            *(float4*)&a[4] = *(const float4*)&As[kk][ty*8+4];
            *(float4*)&b[0] = *(const float4*)&Bs[kk][tx*8];
            *(float4*)&b[4] = *(const float4*)&Bs[kk][tx*8+4];
#pragma unroll
            for (int i = 0; i < 8; i++)
#pragma unroll
                for (int j = 0; j < 8; j++) acc[i][j] += a[i] * b[j];
        }
        __syncthreads();
    }
#pragma unroll
    for (int i = 0; i < 8; i++) {
        size_t row = (size_t)byn * 128 + ty*8 + i;
#pragma unroll
        for (int j = 0; j < 8; j += 4) {
            int col = bxn * 128 + tx*8 + j;
            float4 o;
            o.x = alpha * acc[i][j+0] + bias[col+0];
            o.y = alpha * acc[i][j+1] + bias[col+1];
            o.z = alpha * acc[i][j+2] + bias[col+2];
            o.w = alpha * acc[i][j+3] + bias[col+3];
            *(float4*)(C + row * (size_t)N + col) = o;
        }
    }
}

// ---------------- plain SGEMM (Hp) — proven fp32-roofline version ---------------
__global__ __launch_bounds__(256, 2)
void sgemm_nt(const float* __restrict__ A, const float* __restrict__ Bm,
              float* __restrict__ C, const float* __restrict__ bias,
              int M, int N, int K, float alpha)
{
    __shared__ float As[16][128];
    __shared__ float Bs[16][128];
    const int tid = threadIdx.x;
    const int tx = tid & 15, ty = tid >> 4;
    const float* Ab = A + (size_t)blockIdx.y * 128 * K;
    const float* Bb = Bm + (size_t)blockIdx.x * 128 * K;

    float acc[8][8];
#pragma unroll
    for (int i = 0; i < 8; i++)
#pragma unroll
        for (int j = 0; j < 8; j++) acc[i][j] = 0.f;

    for (int kt = 0; kt < K; kt += 16) {
#pragma unroll
        for (int r = 0; r < 2; r++) {
            int f   = tid + r * 256;
            int row = f >> 2;
            int c4  = (f & 3) << 2;
            float4 va = *(const float4*)(Ab + (size_t)row * K + kt + c4);
            As[c4+0][row] = va.x; As[c4+1][row] = va.y;
            As[c4+2][row] = va.z; As[c4+3][row] = va.w;
            float4 vb = *(const float4*)(Bb + (size_t)row * K + kt + c4);
            Bs[c4+0][row] = vb.x; Bs[c4+1][row] = vb.y;
            Bs[c4+2][row] = vb.z; Bs[c4+3][row] = vb.w;
        }
        __syncthreads();
#pragma unroll
        for (int kk = 0; kk < 16; kk++) {
            float a[8], b[8];
            *(float4*)&a[0] = *(const float4*)&As[kk][ty*8];
            *(float4*)&a[4] = *(const float4*)&As[kk][ty*8+4];
            *(float4*)&b[0] = *(const float4*)&Bs[kk][tx*8];
            *(float4*)&b[4] = *(const float4*)&Bs[kk][tx*8+4];
#pragma unroll
            for (int i = 0; i < 8; i++)
#pragma unroll
                for (int j = 0; j < 8; j++) acc[i][j] += a[i] * b[j];
        }
        __syncthreads();
    }
#pragma unroll
    for (int i = 0; i < 8; i++) {
        size_t row = (size_t)blockIdx.y * 128 + ty*8 + i;
#pragma unroll
        for (int j = 0; j < 8; j += 4) {
            int col = blockIdx.x * 128 + tx*8 + j;
            float4 o;
            o.x = alpha * acc[i][j+0] + bias[col+0];
            o.y = alpha * acc[i][j+1] + bias[col+1];
            o.z = alpha * acc[i][j+2] + bias[col+2];
            o.w = alpha * acc[i][j+3] + bias[col+3];
            *(float4*)(C + row * (size_t)N + col) = o;
        }
    }
}

// ---------------- launch #3: argmin (reference-exact) + gather + mse -----------
__global__ void argmin_kernel(const float* __restrict__ codebook,
                              float* __restrict__ dout) {
    int wid = threadIdx.x >> 5, lane = threadIdx.x & 31;
    int row = blockIdx.x * 8 + wid;
    __shared__ float part[8];
    __shared__ float cn_s[Sn];
    if (threadIdx.x < Sn) cn_s[threadIdx.x] = g_cnorm[threadIdx.x];
    __syncthreads();

    const float rn = g_rnorm[row];
    float bv = 3.4e38f; int bi = 0;
#pragma unroll
    for (int j = 0; j < 8; j++) {
        int i = j * 32 + lane;
        float dot2 = g_dots[(size_t)row * Sn + i];
        float v = __fadd_rn(__fsub_rn(rn, dot2), cn_s[i]);
        if (v < bv) { bv = v; bi = i; }
    }
#pragma unroll
    for (int off = 16; off; off >>= 1) {
        float ov = __shfl_xor_sync(0xffffffffu, bv, off);
        int   oi = __shfl_xor_sync(0xffffffffu, bi, off);
        if (ov < bv || (ov == bv && oi < bi)) { bv = ov; bi = oi; }
    }
    if (lane == 0) {
        g_idx[row] = bi;
        dout[IOFF + row] = (float)bi;
        part[wid] = bv;
    }
    const float4* c4 = (const float4*)(codebook + (size_t)bi * Dn);
    float4* o4 = (float4*)(dout + (size_t)row * Dn);
#pragma unroll
    for (int j = 0; j < 8; j++) o4[j*32 + lane] = __ldg(c4 + j*32 + lane);

    __syncthreads();
    if (threadIdx.x == 0) {
        float s = 0.f;
#pragma unroll
        for (int w = 0; w < 8; w++) s += part[w];
        g_mse_arr[blockIdx.x] = s;
    }
}

// ---------------- launch #4 (profiled): persistent GRU step-GEMM ---------------
// R13 GEMM shape (proven lowest L1): 144 CTAs = 24 m-tiles(128) x 6 k-splits
// (176x4,160x2), W tile in smem once, per-step h slice staged, 128x32xK smem
// GEMM. New vs R13: (1) distributed 16-counter barriers; (2) partials in
// [ks][m][b] layout -> coalesced gate reads; (3) gate phase spread over CTAs
// 0..127 (warp = one d, lane = b) with code/GI/hprev prefetched pre-barrier.
__device__ __forceinline__ unsigned ld_relaxed_u32(const unsigned* p) {
    unsigned v;
    asm volatile("ld.relaxed.gpu.u32 %0, [%1];" : "=r"(v) : "l"(p) : "memory");
    return v;
}
__device__ __forceinline__ void gbar(int bid, int tid, unsigned tgt) {
    __syncthreads();
    if (tid == 0) {
        __threadfence();                             // release CTA's stores
        atomicAdd(&g_ctr[(bid & 15) * 64], 1u);
        unsigned s;
        do {
            s = 0;
#pragma unroll
            for (int i = 0; i < 16; i++) s += ld_relaxed_u32(&g_ctr[i * 64]);
        } while (s < tgt);
        __threadfence();                             // acquire
    }
    __syncthreads();
}

__global__ __launch_bounds__(256, 1)
void gru_step(const float* __restrict__ Wf, const float* __restrict__ bhh)
{
    extern __shared__ float sm[];
    float* Ws = sm + WS_OFF;            // [ksz][132]
    float* hs = sm + HS_OFF;            // [ksz][36]
    float* mg = sm + MG_OFF;            // [128][36] team merge buf

    const int tid  = threadIdx.x;
    const int team = tid >> 7, ttid = tid & 127;
    const int tm = ttid >> 3, tb = ttid & 7;
    const int bid = blockIdx.x;
    const int mt = bid / 6, ks = bid - mt * 6;
    const int ksz  = (ks < 4) ? 176 : 160;
    const int k0   = (ks < 4) ? ks * 176 : 704 + (ks - 4) * 160;
    const int m0   = mt * 128;
    const int kmid = (ks < 4) ? 96 : 80;
    const int kbeg = team ? kmid : 0;
    const int kend = team ? ksz : kmid;

    // gate role: CTAs 0..127, warp = one d, lane = b
    const bool gact = (bid < 128);
    const int  gd   = bid * 8 + (tid >> 5);
    const int  gb   = tid & 31;
    float bh0 = 0.f, bh1 = 0.f, bh2 = 0.f;
    if (gact) {
        bh0 = __ldg(bhh + gd);
        bh1 = __ldg(bhh + Dn + gd);
        bh2 = __ldg(bhh + 2 * Dn + gd);
    }

    // ---- stage W tile once (transposed into [k][m], padded rows) ----
    for (int m = 0; m < 128; m++)
        for (int kk = tid; kk < ksz; kk += 256)
            Ws[kk*WS_STRIDE + m] = __ldg(Wf + (size_t)(m0 + m) * Dn + k0 + kk);
    __syncthreads();

    for (int t = 0; t < Tn; t++) {
        // ---- stage h slice: g_hkb[k][b] (.cg, cross-SM data) ----
        for (int i = tid; i < ksz * 8; i += 256) {
            int kk = i >> 3, bq = i & 7;
            float4 v = __ldcg((const float4*)(g_hkb + (k0 + kk) * 32 + bq * 4));
            float* dst = hs + kk * HS_STRIDE + bq * 4;
            dst[0] = v.x; dst[1] = v.y; dst[2] = v.z; dst[3] = v.w;
        }

        // ---- gate prefetch (pre-barrier; hprev slot is same-thread-owned) ----
        float gi0 = 0.f, gi1 = 0.f, gi2 = 0.f, hprev = 0.f;
        if (gact) {
            int code = __ldg(g_idx + gb * Tn + t);
            const float* gi = g_GI + (size_t)code * (3 * Dn);
            gi0   = __ldg(gi + gd);
            gi1   = __ldg(gi + Dn + gd);
            gi2   = __ldg(gi + 2 * Dn + gd);
            hprev = g_hkb[gd * 32 + gb];
        }
        __syncthreads();

        // ---- 128x32 GEMM over this team's k range ----
        float acc[8][4];
#pragma unroll
        for (int i = 0; i < 8; i++)
#pragma unroll
            for (int j = 0; j < 4; j++) acc[i][j] = 0.f;

#pragma unroll 2
        for (int kk = kbeg; kk < kend; kk++) {
            float4 w0 = *(const float4*)(Ws + kk*WS_STRIDE + tm*8);
            float4 w1 = *(const float4*)(Ws + kk*WS_STRIDE + tm*8 + 4);
            float4 hv = *(const float4*)(hs + kk*HS_STRIDE + tb*4);
            float wa[8] = {w0.x, w0.y, w0.z, w0.w, w1.x, w1.y, w1.z, w1.w};
            float hb[4] = {hv.x, hv.y, hv.z, hv.w};
#pragma unroll
            for (int i = 0; i < 8; i++)
#pragma unroll
                for (int j = 0; j < 4; j++) acc[i][j] += wa[i] * hb[j];
        }

        // ---- merge teams + store partials [ks][m][b] ----
        if (team == 1) {
#pragma unroll
            for (int i = 0; i < 8; i++) {
                float4 o; o.x = acc[i][0]; o.y = acc[i][1]; o.z = acc[i][2]; o.w = acc[i][3];
                *(float4*)(mg + (tm*8 + i) * 36 + tb*4) = o;
            }
        }
        __syncthreads();
        if (team == 0) {
#pragma unroll
            for (int i = 0; i < 8; i++) {
                float4 o = *(const float4*)(mg + (tm*8 + i) * 36 + tb*4);
                float4 s;
                s.x = acc[i][0] + o.x; s.y = acc[i][1] + o.y;
                s.z = acc[i][2] + o.z; s.w = acc[i][3] + o.w;
                *(float4*)(&g_part2[ks][m0 + tm*8 + i][tb*4]) = s;
            }
        }
        gbar(bid, tid, (unsigned)GCTAS * (unsigned)(2*t + 1));

        // ---- gates: 128 CTAs x 8 d x 32 b, fully coalesced partial reads ----
        if (gact) {
            float sr = bh0 + gi0, sz = bh1 + gi1, sn = bh2;
#pragma unroll
            for (int s = 0; s < 6; s++) {
                sr += __ldcg(&g_part2[s][gd][gb]);
                sz += __ldcg(&g_part2[s][Dn + gd][gb]);
                sn += __ldcg(&g_part2[s][2*Dn + gd][gb]);
            }
            float r = 1.f / (1.f + expf(-sr));
            float z = 1.f / (1.f + expf(-sz));
            float n = tanhf(gi2 + r * sn);
            float hn = (1.f - z) * n + z * hprev;
            g_hkb[gd * 32 + gb] = hn;
            g_Hbuf[(size_t)(t + 1) * (Bn * Dn) + gb * Dn + gd] = hn;
        }
        gbar(bid, tid, (unsigned)GCTAS * (unsigned)(2*t + 2));
    }
}

// ---------------- CP loss per (k,t) ---------------------------------------------
__global__ void cploss_kernel(const float* __restrict__ features,
                              const int* __restrict__ neg_idx)
{
    int t  = blockIdx.x;
    int kf = blockIdx.y;
    int k  = kf + 1;
    int slot = kf * (Tn - 1) + t;
    if (t >= Tn - k) { if (threadIdx.x == 0) g_cp_arr[slot] = 0.f; return; }

    __shared__ float sig_s[Bn];
    int wid = threadIdx.x >> 5, lane = threadIdx.x & 31;
#pragma unroll
    for (int bi = 0; bi < 4; bi++) {
        int b = wid * 4 + bi;
        const float4* hp = (const float4*)(g_Hp + ((size_t)t * Bn + b) * Dn);
        const float4* fp = (const float4*)(features + ((size_t)b * Tn + (t + k)) * Dn);
        int bneg = neg_idx[((size_t)kf * Tn + t) * Bn + b];
        const float4* fn = (const float4*)(features + ((size_t)bneg * Tn + t) * Dn);
        float s = 0.f;
#pragma unroll
        for (int j = 0; j < 8; j++) {
            float4 h4 = hp[j*32 + lane];
            float4 p4 = fp[j*32 + lane];
            float4 n4 = fn[j*32 + lane];
            s += h4.x*(p4.x-n4.x) + h4.y*(p4.y-n4.y)
               + h4.z*(p4.z-n4.z) + h4.w*(p4.w-n4.w);
        }
#pragma unroll
        for (int off = 16; off; off >>= 1) s += __shfl_xor_sync(0xffffffffu, s, off);
        if (lane == 0) sig_s[b] = 1.f / (1.f + expf(-s));
    }
    __syncthreads();
    if (threadIdx.x == 0) {
        float m = 0.f;
#pragma unroll
        for (int b = 0; b < Bn; b++) m += sig_s[b];
        g_cp_arr[slot] = -logf(m * (1.f / (float)Bn));
    }
}

// ---------------- final deterministic reduction ----------------------------------
__global__ void finalize_kernel(float* __restrict__ dout) {
    __shared__ float red[256];
    int tid = threadIdx.x;
    float s = 0.f;
    for (int i = tid; i < KF*(Tn-1); i += 256) s += g_cp_arr[i];
    red[tid] = s; __syncthreads();
    for (int o = 128; o; o >>= 1) { if (tid < o) red[tid] += red[tid+o]; __syncthreads(); }
    float cp = red[0]; __syncthreads();
    float m = 0.f;
    for (int i = tid; i < Mrows/8; i += 256) m += g_mse_arr[i];
    red[tid] = m; __syncthreads();
    for (int o = 128; o; o >>= 1) { if (tid < o) red[tid] += red[tid+o]; __syncthreads(); }
    if (tid == 0) {
        float mse = red[0] / ((float)Mrows * (float)Dn);
        dout[LOFF] = cp / (float)(KF * (Tn - KF)) + 1.25f * mse;
    }
}

// ---------------- launch ----------------------------------------------------------
extern "C" void kernel_launch(void* const* d_in, const int* in_sizes, int n_in,
                              void* d_out, int out_size) {
    (void)in_sizes; (void)n_in; (void)out_size;
    const float* features = (const float*)d_in[0];
    const float* codebook = (const float*)d_in[1];
    const float* W_ih     = (const float*)d_in[2];
    const float* W_hh     = (const float*)d_in[3];
    const float* b_ih     = (const float*)d_in[4];
    const float* b_hh     = (const float*)d_in[5];
    const float* W_p      = (const float*)d_in[6];
    const float* b_p      = (const float*)d_in[7];
    const int*   neg_idx  = (const int*)d_in[8];
    float* dout = (float*)d_out;

    void *p_dots, *p_GI, *p_Hbuf, *p_Hp, *p_zb;
    cudaGetSymbolAddress(&p_dots, g_dots);
    cudaGetSymbolAddress(&p_GI,   g_GI);
    cudaGetSymbolAddress(&p_Hbuf, g_Hbuf);
    cudaGetSymbolAddress(&p_Hp,   g_Hp);
    cudaGetSymbolAddress(&p_zb,   g_zbias);
    const float* p_H = (const float*)p_Hbuf + (size_t)Bn * Dn;  // slots 1..Tn

    cudaFuncSetAttribute(gru_step,
        cudaFuncAttributeMaxDynamicSharedMemorySize, GRU_SMEM);

    // #1: rownorms + h/ctr init
    prep_kernel<<<4096 + 32 + 256, 256>>>(features, codebook);

    // #2: fused GEMM — dots = 2*F C^T (bit-identical chain) and GI
    sgemm_fused<<<DOTS_BLKS + 48, 256>>>(
        features, codebook, (float*)p_dots, (const float*)p_zb, Dn, 2.0f, Sn,
        codebook, W_ih,     (float*)p_GI,   b_ih,               Dn, 1.0f, 3*Dn);

    // #3: argmin + quantized gather + mse partials
    argmin_kernel<<<Mrows/8, 256>>>(codebook, dout);

    // #4 (profiled): persistent GRU step-GEMM (distributed barriers, spread gates)
    gru_step<<<GCTAS, 256, GRU_SMEM>>>(W_hh, b_hh);

    // #5: Hp = H @ W_p^T + b_p
    sgemm_nt<<<dim3(Dn/128, Mrows/128), 256>>>(
        p_H, W_p, (float*)p_Hp, b_p, Mrows, Dn, Dn, 1.0f);

    // #6: CP loss terms
    cploss_kernel<<<dim3(Tn-1, KF), 256>>>(features, neg_idx);

    // #7: deterministic final reduction
    finalize_kernel<<<1, 256>>>(dout);
}